// round 16
// baseline (speedup 1.0000x reference)
#include <cuda_runtime.h>
#include <cuda_fp16.h>
#include <cstdint>
#include <cstddef>

// ---------------------------------------------------------------------------
// Problem constants: B=4, NQ=NK=4096, D=256
// d_out = [ h: 4*4096*256 | attn: 4*4096*4096 ]
// ---------------------------------------------------------------------------

// Scratch (device globals: allocation inside kernel_launch is forbidden)
__device__ __half g_xh [4 * 4096 * 256];
__device__ __half g_qh [4 * 4096 * 256];
__device__ __half g_q  [4 * 4096 * 256];
__device__ __half g_k  [4 * 4096 * 256];
__device__ __half g_vt [4 * 4096 * 256];   // V^T, written directly by V proj
__device__ __half g_t0 [4 * 4096 * 256];
__device__ __half g_w  [6][256 * 256];
__device__ __half g_ah [(size_t)4 * 4096 * 4096];   // fp16 scores, then attn

static __device__ __forceinline__ uint32_t smem_u32(const void* p) {
    uint32_t a;
    asm("{ .reg .u64 t; cvta.to.shared.u64 t, %1; cvt.u32.u64 %0, t; }"
        : "=r"(a) : "l"(p));
    return a;
}
static __device__ __forceinline__ uint32_t f2h2(float x, float y) {
    uint32_t r;
    asm("cvt.rn.f16x2.f32 %0, %1, %2;" : "=r"(r) : "f"(y), "f"(x));
    return r;
}
static __device__ __forceinline__ void cp16(uint32_t s, const void* g) {
    asm volatile("cp.async.cg.shared.global [%0], [%1], 16;" :: "r"(s), "l"(g));
}
#define CP_COMMIT() asm volatile("cp.async.commit_group;" ::: "memory")
#define CP_WAIT(n)  asm volatile("cp.async.wait_group %0;" :: "n"(n) : "memory")

// epilogue paired store: fp32 or fp16 destination
static __device__ __forceinline__ void store2(float* C, size_t idx, float x, float y) {
    *(float2*)(C + idx) = make_float2(x, y);
}
static __device__ __forceinline__ void store2(__half* C, size_t idx, float x, float y) {
    *(__half2*)(C + idx) = __floats2half2_rn(x, y);
}

// ===========================================================================
// HMMA fp16 NT GEMM core: C[M,N] = alpha * A[M,K] * B[N,K]^T (+bias, +relu)
//   CTA tile 128x128, BK=32; 8 warps = 2(m) x 4(n); warp tile 64x32.
//   4-stage circular cp.async pipeline, one __syncthreads per chunk,
//   prefetch distance 3 (CP_WAIT(2)). 2 CTAs/SM (80 KB smem each).
//   Smem rows = 32 fp16 + 8 pad = 80B: stride 5 mod 8 in 16B banks
//   -> conflict-free ldmatrix by construction. B frags via ldmatrix.x4.
//   transC=1 (V projection): writes C^T laid out as [batch][N=256][4096].
// ===========================================================================
#define H_MAT   (128 * 40)           // 5120 halfs = 10240 B per matrix
#define STAGE_B (2 * H_MAT * 2)      // A+B bytes per stage = 20480
#define NSTAGE  4
#define GEMM_SMEM (NSTAGE * STAGE_B) // 81920 B dynamic

template <typename TOut>
static __device__ __forceinline__ void gemm_core(
    const __half* __restrict__ A, const __half* __restrict__ B,
    const float* __restrict__ bias, TOut* __restrict__ C,
    int M, int N, int K, float alpha, int relu, int transC, __half* smd)
{
    const int m0 = blockIdx.y * 128;
    const int n0 = blockIdx.x * 128;
    const int tid = threadIdx.x;
    const int w = tid >> 5;
    const int l = tid & 31;

    // ---- async loader mapping: row w*16+(l&15), 16B-chunks {2*(l>>4), +1}
    const int lrow = w * 16 + (l & 15);
    const int lc   = (l >> 4) * 2;
    const uint32_t smem_base = smem_u32(smd);
    const uint32_t sa = smem_base + (uint32_t)(lrow * 80 + lc * 16);
    const uint32_t sb = sa + (uint32_t)(H_MAT * 2);
    const __half* ag = A + (size_t)(m0 + lrow) * (size_t)K + lc * 8;
    const __half* bg = B + (size_t)(n0 + lrow) * (size_t)K + lc * 8;

    auto copy_chunk = [&](int c, int st) {
        const uint32_t off = (uint32_t)st * STAGE_B;
        const __half* a = ag + c * 32;
        const __half* b = bg + c * 32;
        cp16(sa + off, a);      cp16(sa + off + 16, a + 8);
        cp16(sb + off, b);      cp16(sb + off + 16, b + 8);
    };

    // ---- compute mapping: warp tile 64(m) x 32(n)
    const int wm = (w & 1) * 64;
    const int wn = (w >> 1) * 32;
    const uint32_t aoff = (uint32_t)((wm + (l & 15)) * 80 + (l >> 4) * 16);
    const uint32_t boff = (uint32_t)((wn + (l & 7) + ((l >> 4) << 3)) * 80
                                     + ((l >> 3) & 1) * 16);

    float acc[4][4][4];
#pragma unroll
    for (int i = 0; i < 4; i++)
#pragma unroll
        for (int j = 0; j < 4; j++)
#pragma unroll
            for (int q = 0; q < 4; q++) acc[i][j][q] = 0.0f;

    const int nch = K / 32;          // >= 8 for all shapes here

    // prologue: stages 0,1,2 <- chunks 0,1,2
    copy_chunk(0, 0); CP_COMMIT();
    copy_chunk(1, 1); CP_COMMIT();
    copy_chunk(2, 2); CP_COMMIT();

    int st_cmp = 0;
    int st_cpy = 3;
    for (int c = 0; c < nch; c++) {
        CP_WAIT(2);
        __syncthreads();

        if (c + 3 < nch) copy_chunk(c + 3, st_cpy);
        CP_COMMIT();

        const uint32_t aB = smem_base + (uint32_t)st_cmp * STAGE_B;
        const uint32_t bB = aB + (uint32_t)(H_MAT * 2);
#pragma unroll
        for (int s = 0; s < 2; s++) {
            uint32_t af[4][4];
#pragma unroll
            for (int ma = 0; ma < 4; ma++) {
                const uint32_t addr = aB + aoff + (uint32_t)(ma * 16 * 80 + s * 32);
                asm volatile(
                    "ldmatrix.sync.aligned.m8n8.x4.shared.b16 {%0,%1,%2,%3}, [%4];"
                    : "=r"(af[ma][0]), "=r"(af[ma][1]),
                      "=r"(af[ma][2]), "=r"(af[ma][3])
                    : "r"(addr));
            }
            uint32_t bq[2][4];
#pragma unroll
            for (int p = 0; p < 2; p++) {
                const uint32_t addr = bB + boff + (uint32_t)(p * 16 * 80 + s * 32);
                asm volatile(
                    "ldmatrix.sync.aligned.m8n8.x4.shared.b16 {%0,%1,%2,%3}, [%4];"
                    : "=r"(bq[p][0]), "=r"(bq[p][1]),
                      "=r"(bq[p][2]), "=r"(bq[p][3])
                    : "r"(addr));
            }
#pragma unroll
            for (int ma = 0; ma < 4; ma++)
#pragma unroll
                for (int na = 0; na < 4; na++) {
                    const uint32_t b0 = bq[na >> 1][(na & 1) * 2];
                    const uint32_t b1 = bq[na >> 1][(na & 1) * 2 + 1];
                    asm volatile(
                        "mma.sync.aligned.m16n8k16.row.col.f32.f16.f16.f32 "
                        "{%0,%1,%2,%3}, {%4,%5,%6,%7}, {%8,%9}, {%0,%1,%2,%3};"
                        : "+f"(acc[ma][na][0]), "+f"(acc[ma][na][1]),
                          "+f"(acc[ma][na][2]), "+f"(acc[ma][na][3])
                        : "r"(af[ma][0]), "r"(af[ma][1]),
                          "r"(af[ma][2]), "r"(af[ma][3]),
                          "r"(b0), "r"(b1));
                }
        }
        st_cmp = (st_cmp == NSTAGE - 1) ? 0 : st_cmp + 1;
        st_cpy = (st_cpy == NSTAGE - 1) ? 0 : st_cpy + 1;
    }

    // ---- epilogue
    const int erow = m0 + wm + (l >> 2);
    const int ecol = n0 + wn + (l & 3) * 2;
#pragma unroll
    for (int ma = 0; ma < 4; ma++) {
        const int r = erow + ma * 16;
#pragma unroll
        for (int na = 0; na < 4; na++) {
            const int cc = ecol + na * 8;
            float2 bb = make_float2(0.f, 0.f);
            if (bias) bb = *(const float2*)(bias + cc);
            float lx = alpha * acc[ma][na][0] + bb.x;
            float ly = alpha * acc[ma][na][1] + bb.y;
            float hx = alpha * acc[ma][na][2] + bb.x;
            float hy = alpha * acc[ma][na][3] + bb.y;
            if (relu) {
                lx = fmaxf(lx, 0.f); ly = fmaxf(ly, 0.f);
                hx = fmaxf(hx, 0.f); hy = fmaxf(hy, 0.f);
            }
            if (!transC) {
                store2(C, (size_t)r * (size_t)N + cc, lx, ly);
                store2(C, (size_t)(r + 8) * (size_t)N + cc, hx, hy);
            } else {
                const size_t b0 = ((size_t)(r >> 12) * 256 + cc) * 4096 + (r & 4095);
                C[b0]        = (TOut)lx;
                C[b0 + 4096] = (TOut)ly;
                const int r8 = r + 8;
                const size_t b1 = ((size_t)(r8 >> 12) * 256 + cc) * 4096 + (r8 & 4095);
                C[b1]        = (TOut)hx;
                C[b1 + 4096] = (TOut)hy;
            }
        }
    }
}

// Generic batched GEMM kernel (QK^T, AV)
template <typename TOut>
__global__ void __launch_bounds__(256, 2) gemm_h_nt(
    const __half* __restrict__ A, const __half* __restrict__ B,
    const float* __restrict__ bias, TOut* __restrict__ C,
    int M, int N, int K,
    long long sA, long long sB, long long sC,
    float alpha, int relu)
{
    extern __shared__ __align__(16) __half smd[];
    A += (size_t)blockIdx.z * (size_t)sA;
    B += (size_t)blockIdx.z * (size_t)sB;
    C += (size_t)blockIdx.z * (size_t)sC;
    gemm_core<TOut>(A, B, bias, C, M, N, K, alpha, relu, 0, smd);
}

// Fused q/k/v projections: grid.z selects {q, k, v}; v written transposed.
__global__ void __launch_bounds__(256, 2) qkv_proj(
    const __half* __restrict__ qh, const __half* __restrict__ xh,
    const __half* __restrict__ wh,
    const float* __restrict__ bq, const float* __restrict__ bk,
    const float* __restrict__ bv,
    __half* __restrict__ q, __half* __restrict__ k, __half* __restrict__ vt)
{
    extern __shared__ __align__(16) __half smd[];
    const int z = blockIdx.z;
    const __half* A = (z == 0) ? qh : xh;
    const __half* W = wh + z * 65536;
    const float* bias = (z == 0) ? bq : (z == 1) ? bk : bv;
    __half* C = (z == 0) ? q : (z == 1) ? k : vt;
    gemm_core<__half>(A, W, bias, C, 16384, 256, 256, 1.0f, 0, z == 2, smd);
}

// ===========================================================================
// Fused 3-layer MLP: h = relu(relu(relu(in W1^T+b1) W2^T+b2) W3^T+b3)
//   256 CTAs x 64 rows; activations resident in smem (padded 528B rows:
//   stride 33 chunks == 1 mod 8 -> conflict-free ldmatrix phases).
//   Per layer: stream W (256 rows x 32 fp16 chunks) via 3-stage cp.async
//   pipeline; A-fragments ldmatrix'd straight from resident activations;
//   post-loop barrier, write relu(acc+bias) back into the SAME buffer
//   (accumulators are in registers), barrier, next layer.
//   Warps: 2(m) x 4(n); warp tile 32 x 64. Layer 3 writes fp32 to hout.
// ===========================================================================
#define MLP_ROWS   64
#define ACT_STRIDE 264                         // halfs per row (256 + 8 pad)
#define ACT_BYTES  (MLP_ROWS * ACT_STRIDE * 2) // 33792
#define WSTAGE_B   (256 * 80)                  // 20480 per W stage
#define MLP_NST    3
#define MLP_SMEM   (ACT_BYTES + MLP_NST * WSTAGE_B)   // 95232 B

__global__ void __launch_bounds__(256, 2) mlp_fused(
    const __half* __restrict__ in,     // t0 [16384][256] fp16
    const __half* __restrict__ wh,     // W1 at +0, W2 +65536, W3 +131072
    const float* __restrict__ b1, const float* __restrict__ b2,
    const float* __restrict__ b3,
    float* __restrict__ hout)          // [16384][256] fp32
{
    extern __shared__ __align__(16) __half smd[];
    const int r0 = blockIdx.x * MLP_ROWS;
    const int tid = threadIdx.x;
    const int w = tid >> 5;
    const int l = tid & 31;

    const uint32_t base  = smem_u32(smd);
    const uint32_t wbase = base + (uint32_t)ACT_BYTES;

    // ---- load input block 64 x 256 fp16 into resident activation smem
#pragma unroll
    for (int i = 0; i < 8; i++) {
        const int v = tid + i * 256;            // vec8 index, 2048 total
        const int row = v >> 5, c8 = v & 31;
        cp16(base + (uint32_t)(row * 528 + c8 * 16),
             in + (size_t)(r0 + row) * 256 + c8 * 8);
    }
    CP_COMMIT();

    // ---- W loader: thread t covers W row t (N=256), 4x16B per chunk
    const uint32_t sw = wbase + (uint32_t)(tid * 80);

    // ---- compute mapping: warp tile 32(m) x 64(n)
    const int wm = (w & 1) * 32;
    const int wn = (w >> 1) * 64;
    const uint32_t aoff = (uint32_t)((wm + (l & 15)) * 528 + (l >> 4) * 16);
    const uint32_t boff = (uint32_t)((wn + (l & 7) + ((l >> 4) << 3)) * 80
                                     + ((l >> 3) & 1) * 16);
    const int erow = wm + (l >> 2);
    const int ecol = wn + (l & 3) * 2;

#pragma unroll 1
    for (int layer = 0; layer < 3; layer++) {
        const __half* W = wh + layer * 65536;
        const float* bias = (layer == 0) ? b1 : (layer == 1) ? b2 : b3;

        float acc[2][8][4];
#pragma unroll
        for (int i = 0; i < 2; i++)
#pragma unroll
            for (int j = 0; j < 8; j++)
#pragma unroll
                for (int q = 0; q < 4; q++) acc[i][j][q] = 0.0f;

        // prologue: W chunks 0,1 -> stages 0,1
        cp16(sw,      W + tid * 256);       cp16(sw + 16, W + tid * 256 + 8);
        cp16(sw + 32, W + tid * 256 + 16);  cp16(sw + 48, W + tid * 256 + 24);
        CP_COMMIT();
        {
            const uint32_t s1 = sw + WSTAGE_B;
            const __half* wg = W + tid * 256 + 32;
            cp16(s1, wg); cp16(s1 + 16, wg + 8);
            cp16(s1 + 32, wg + 16); cp16(s1 + 48, wg + 24);
        }
        CP_COMMIT();

        int st_cmp = 0, st_cpy = 2;
#pragma unroll 1
        for (int c = 0; c < 8; c++) {
            CP_WAIT(1);
            __syncthreads();

            if (c + 2 < 8) {
                const uint32_t sd = sw + (uint32_t)st_cpy * WSTAGE_B;
                const __half* wg = W + tid * 256 + (c + 2) * 32;
                cp16(sd, wg); cp16(sd + 16, wg + 8);
                cp16(sd + 32, wg + 16); cp16(sd + 48, wg + 24);
            }
            CP_COMMIT();

            const uint32_t bB = wbase + (uint32_t)st_cmp * WSTAGE_B;
#pragma unroll
            for (int s = 0; s < 2; s++) {
                uint32_t af[2][4];
#pragma unroll
                for (int ma = 0; ma < 2; ma++) {
                    const uint32_t addr = base + aoff
                        + (uint32_t)(ma * 16 * 528 + c * 64 + s * 32);
                    asm volatile(
                        "ldmatrix.sync.aligned.m8n8.x4.shared.b16 {%0,%1,%2,%3}, [%4];"
                        : "=r"(af[ma][0]), "=r"(af[ma][1]),
                          "=r"(af[ma][2]), "=r"(af[ma][3])
                        : "r"(addr));
                }
                uint32_t bq[4][4];
#pragma unroll
                for (int p = 0; p < 4; p++) {
                    const uint32_t addr = bB + boff + (uint32_t)(p * 16 * 80 + s * 32);
                    asm volatile(
                        "ldmatrix.sync.aligned.m8n8.x4.shared.b16 {%0,%1,%2,%3}, [%4];"
                        : "=r"(bq[p][0]), "=r"(bq[p][1]),
                          "=r"(bq[p][2]), "=r"(bq[p][3])
                        : "r"(addr));
                }
#pragma unroll
                for (int ma = 0; ma < 2; ma++)
#pragma unroll
                    for (int na = 0; na < 8; na++) {
                        const uint32_t f0 = bq[na >> 1][(na & 1) * 2];
                        const uint32_t f1 = bq[na >> 1][(na & 1) * 2 + 1];
                        asm volatile(
                            "mma.sync.aligned.m16n8k16.row.col.f32.f16.f16.f32 "
                            "{%0,%1,%2,%3}, {%4,%5,%6,%7}, {%8,%9}, {%0,%1,%2,%3};"
                            : "+f"(acc[ma][na][0]), "+f"(acc[ma][na][1]),
                              "+f"(acc[ma][na][2]), "+f"(acc[ma][na][3])
                            : "r"(af[ma][0]), "r"(af[ma][1]),
                              "r"(af[ma][2]), "r"(af[ma][3]),
                              "r"(f0), "r"(f1));
                    }
            }
            st_cmp = (st_cmp == MLP_NST - 1) ? 0 : st_cmp + 1;
            st_cpy = (st_cpy == MLP_NST - 1) ? 0 : st_cpy + 1;
        }

        // all reads of activations + W done before overwriting activations
        __syncthreads();

#pragma unroll
        for (int ma = 0; ma < 2; ma++) {
            const int r = erow + ma * 16;
#pragma unroll
            for (int na = 0; na < 8; na++) {
                const int cc = ecol + na * 8;
                const float2 bb = *(const float2*)(bias + cc);
                float lx = fmaxf(acc[ma][na][0] + bb.x, 0.f);
                float ly = fmaxf(acc[ma][na][1] + bb.y, 0.f);
                float hx = fmaxf(acc[ma][na][2] + bb.x, 0.f);
                float hy = fmaxf(acc[ma][na][3] + bb.y, 0.f);
                if (layer < 2) {
                    *(__half2*)(smd + r * ACT_STRIDE + cc) =
                        __floats2half2_rn(lx, ly);
                    *(__half2*)(smd + (r + 8) * ACT_STRIDE + cc) =
                        __floats2half2_rn(hx, hy);
                } else {
                    store2(hout, (size_t)(r0 + r) * 256 + cc, lx, ly);
                    store2(hout, (size_t)(r0 + r + 8) * 256 + cc, hx, hy);
                }
            }
        }
        __syncthreads();    // activations updated before next layer reads/copies
    }
}

// ===========================================================================
// One-shot fp32 -> fp16 conversion of query, x, and the 6 weights.
// Segments (in 8-elem units): query 524288 | x 524288 | 6 x 8192
// ===========================================================================
__global__ void __launch_bounds__(256) f2h_all(
    const float* __restrict__ query, const float* __restrict__ x,
    const float* __restrict__ Wq, const float* __restrict__ Wk,
    const float* __restrict__ Wv, const float* __restrict__ W1,
    const float* __restrict__ W2, const float* __restrict__ W3,
    __half* __restrict__ qh, __half* __restrict__ xh, __half* __restrict__ wh)
{
    const int idx = blockIdx.x * 256 + threadIdx.x;    // vec8 index
    const float* s;
    __half* d;
    int off;
    if (idx < 524288)            { s = query; d = qh; off = idx; }
    else if (idx < 1048576)      { s = x;     d = xh; off = idx - 524288; }
    else {
        const int wv8 = idx - 1048576;                 // 0 .. 49151
        const int wi = wv8 >> 13;                      // weight id 0..5
        off = wv8 & 8191;
        switch (wi) {
            case 0: s = Wq; break;  case 1: s = Wk; break;
            case 2: s = Wv; break;  case 3: s = W1; break;
            case 4: s = W2; break;  default: s = W3; break;
        }
        d = wh + wi * 65536;
    }
    const int i = off * 8;
    float4 u = *(const float4*)(s + i);
    float4 v = *(const float4*)(s + i + 4);
    uint4 o;
    o.x = f2h2(u.x, u.y); o.y = f2h2(u.z, u.w);
    o.z = f2h2(v.x, v.y); o.w = f2h2(v.z, v.w);
    *(uint4*)(d + i) = o;
}

// ---------------------------------------------------------------------------
// Row softmax: reads fp16 scores from ah, writes fp32 attn (output slot) and
// fp16 attn back into ah (for AV). attn[16384][4096].
// ---------------------------------------------------------------------------
static __device__ __forceinline__ float warpMax(float v) {
#pragma unroll
    for (int o = 16; o > 0; o >>= 1) v = fmaxf(v, __shfl_xor_sync(0xffffffffu, v, o));
    return v;
}
static __device__ __forceinline__ float warpSum(float v) {
#pragma unroll
    for (int o = 16; o > 0; o >>= 1) v += __shfl_xor_sync(0xffffffffu, v, o);
    return v;
}

__global__ void __launch_bounds__(256) softmax_rows(
    float* __restrict__ attn, __half* __restrict__ ah)
{
    __shared__ float red[8];
    __shared__ float bcast;
    const size_t row = blockIdx.x;
    float* p = attn + row * 4096;
    __half2* ph = (__half2*)(ah + row * 4096);
    const int tid = threadIdx.x;

    float v[16];
#pragma unroll
    for (int j = 0; j < 8; j++) {
        const float2 f = __half22float2(ph[tid + j * 256]);
        v[2 * j]     = f.x;
        v[2 * j + 1] = f.y;
    }

    float m = v[0];
#pragma unroll
    for (int i = 1; i < 16; i++) m = fmaxf(m, v[i]);
    m = warpMax(m);
    if ((tid & 31) == 0) red[tid >> 5] = m;
    __syncthreads();
    if (tid < 32) {
        float t = (tid < 8) ? red[tid] : -3.4e38f;
        t = warpMax(t);
        if (tid == 0) bcast = t;
    }
    __syncthreads();
    m = bcast;

    float s = 0.0f;
#pragma unroll
    for (int i = 0; i < 16; i++) { v[i] = __expf(v[i] - m); s += v[i]; }
    s = warpSum(s);
    __syncthreads();
    if ((tid & 31) == 0) red[tid >> 5] = s;
    __syncthreads();
    if (tid < 32) {
        float t = (tid < 8) ? red[tid] : 0.0f;
        t = warpSum(t);
        if (tid == 0) bcast = t;
    }
    __syncthreads();
    const float inv = 1.0f / bcast;
#pragma unroll
    for (int j = 0; j < 8; j++) {
        const float r0 = v[2 * j] * inv;
        const float r1 = v[2 * j + 1] * inv;
        *(float2*)(p + 2 * (tid + j * 256)) = make_float2(r0, r1);
        ph[tid + j * 256] = __floats2half2_rn(r0, r1);
    }
}

// ---------------------------------------------------------------------------
// Host launcher (graph-capturable: kernel launches only)
// ---------------------------------------------------------------------------
extern "C" void kernel_launch(void* const* d_in, const int* in_sizes, int n_in,
                              void* d_out, int out_size)
{
    (void)in_sizes; (void)n_in; (void)out_size;
    const float* x     = (const float*)d_in[0];
    const float* query = (const float*)d_in[1];
    const float* Wq = (const float*)d_in[2];  const float* bq = (const float*)d_in[3];
    const float* Wk = (const float*)d_in[4];  const float* bk = (const float*)d_in[5];
    const float* Wv = (const float*)d_in[6];  const float* bv = (const float*)d_in[7];
    const float* W1 = (const float*)d_in[8];  const float* b1 = (const float*)d_in[9];
    const float* W2 = (const float*)d_in[10]; const float* b2 = (const float*)d_in[11];
    const float* W3 = (const float*)d_in[12]; const float* b3 = (const float*)d_in[13];

    float* outp = (float*)d_out;
    float* hout = outp;                                    // [4,4096,256]
    float* attn = outp + (size_t)4 * 4096 * 256;           // [4,4096,4096]

    __half *xh, *qh, *q, *k, *vt, *t0, *wh, *ah;
    cudaGetSymbolAddress((void**)&xh, g_xh);
    cudaGetSymbolAddress((void**)&qh, g_qh);
    cudaGetSymbolAddress((void**)&q,  g_q);
    cudaGetSymbolAddress((void**)&k,  g_k);
    cudaGetSymbolAddress((void**)&vt, g_vt);
    cudaGetSymbolAddress((void**)&t0, g_t0);
    cudaGetSymbolAddress((void**)&wh, g_w);
    cudaGetSymbolAddress((void**)&ah, g_ah);

    cudaFuncSetAttribute(gemm_h_nt<__half>,
                         cudaFuncAttributeMaxDynamicSharedMemorySize, GEMM_SMEM);
    cudaFuncSetAttribute(qkv_proj,
                         cudaFuncAttributeMaxDynamicSharedMemorySize, GEMM_SMEM);
    cudaFuncSetAttribute(mlp_fused,
                         cudaFuncAttributeMaxDynamicSharedMemorySize, MLP_SMEM);

    const int Mtot = 4 * 4096;
    const int S = 4096;
    const dim3 blk(256);

    // ---- one-shot fp32 -> fp16 conversions (query, x, 6 weights)
    f2h_all<<<4288, 256>>>(query, x, Wq, Wk, Wv, W1, W2, W3, qh, xh, wh);

    // ---- fused q/k/v projections; V written transposed into vt
    qkv_proj<<<dim3(2, 128, 3), blk, GEMM_SMEM>>>(qh, xh, wh, bq, bk, bv, q, k, vt);

    // ---- scores = (q @ k^T) / sqrt(D) -> fp16 into ah
    gemm_h_nt<__half><<<dim3(S / 128, S / 128, 4), blk, GEMM_SMEM>>>(
        q, k, nullptr, ah, S, S, 256,
        (long long)S * 256, (long long)S * 256, (long long)S * S, 0.0625f, 0);

    // ---- softmax: fp16 scores -> fp32 attn output + fp16 attn (in ah)
    softmax_rows<<<Mtot, blk>>>(attn, ah);

    // ---- out = attn @ V = attn_h @ (V^T)^T  (fp16 out)
    gemm_h_nt<__half><<<dim3(2, S / 128, 4), blk, GEMM_SMEM>>>(
        ah, vt, nullptr, t0, S, 256, S,
        (long long)S * S, (long long)256 * S, (long long)S * 256, 1.0f, 0);

    // ---- fused 3-layer MLP: t0 -> h (fp32), activations resident in smem
    mlp_fused<<<Mtot / MLP_ROWS, blk, MLP_SMEM>>>(
        t0, wh + 3 * 65536, b1, b2, b3, hout);
}

// round 17
// speedup vs baseline: 1.0436x; 1.0436x over previous
#include <cuda_runtime.h>
#include <cuda_fp16.h>
#include <cstdint>
#include <cstddef>

// ---------------------------------------------------------------------------
// Problem constants: B=4, NQ=NK=4096, D=256
// d_out = [ h: 4*4096*256 | attn: 4*4096*4096 ]
// ---------------------------------------------------------------------------

// Scratch (device globals: allocation inside kernel_launch is forbidden)
__device__ __half g_xh [4 * 4096 * 256];
__device__ __half g_qh [4 * 4096 * 256];
__device__ __half g_q  [4 * 4096 * 256];
__device__ __half g_k  [4 * 4096 * 256];
__device__ __half g_vt [4 * 4096 * 256];   // V^T, written directly by V proj
__device__ __half g_t0 [4 * 4096 * 256];
__device__ __half g_t1 [4 * 4096 * 256];
__device__ __half g_w  [6][256 * 256];
__device__ __half g_ah [(size_t)4 * 4096 * 4096];   // fp16 scores, then attn

static __device__ __forceinline__ uint32_t smem_u32(const void* p) {
    uint32_t a;
    asm("{ .reg .u64 t; cvta.to.shared.u64 t, %1; cvt.u32.u64 %0, t; }"
        : "=r"(a) : "l"(p));
    return a;
}
static __device__ __forceinline__ uint32_t f2h2(float x, float y) {
    uint32_t r;
    asm("cvt.rn.f16x2.f32 %0, %1, %2;" : "=r"(r) : "f"(y), "f"(x));
    return r;
}
static __device__ __forceinline__ void cp16(uint32_t s, const void* g) {
    asm volatile("cp.async.cg.shared.global [%0], [%1], 16;" :: "r"(s), "l"(g));
}
#define CP_COMMIT() asm volatile("cp.async.commit_group;" ::: "memory")
#define CP_WAIT(n)  asm volatile("cp.async.wait_group %0;" :: "n"(n) : "memory")

// epilogue paired store: fp32 or fp16 destination
static __device__ __forceinline__ void store2(float* C, size_t idx, float x, float y) {
    *(float2*)(C + idx) = make_float2(x, y);
}
static __device__ __forceinline__ void store2(__half* C, size_t idx, float x, float y) {
    *(__half2*)(C + idx) = __floats2half2_rn(x, y);
}

// ===========================================================================
// HMMA fp16 NT GEMM core: C[M,N] = alpha * A[M,K] * B[N,K]^T (+bias, +relu)
//   CTA tile 128x128 at (m0, n0), BK=32; 8 warps = 2(m) x 4(n); warp 64x32.
//   4-stage circular cp.async pipeline, one __syncthreads per chunk,
//   prefetch distance 3 (CP_WAIT(2)). 2 CTAs/SM (80 KB smem each).
//   Smem rows = 32 fp16 + 8 pad = 80B: stride 5 mod 8 in 16B banks
//   -> conflict-free ldmatrix by construction. B frags via ldmatrix.x4.
//   transC=1 (V projection): writes C^T laid out as [batch][N=256][4096].
// ===========================================================================
#define H_MAT   (128 * 40)           // 5120 halfs = 10240 B per matrix
#define STAGE_B (2 * H_MAT * 2)      // A+B bytes per stage = 20480
#define NSTAGE  4
#define GEMM_SMEM (NSTAGE * STAGE_B) // 81920 B dynamic

template <typename TOut>
static __device__ __forceinline__ void gemm_core(
    const __half* __restrict__ A, const __half* __restrict__ B,
    const float* __restrict__ bias, TOut* __restrict__ C,
    int N, int K, float alpha, int relu, int transC, __half* smd,
    int m0, int n0)
{
    const int tid = threadIdx.x;
    const int w = tid >> 5;
    const int l = tid & 31;

    // ---- async loader mapping: row w*16+(l&15), 16B-chunks {2*(l>>4), +1}
    const int lrow = w * 16 + (l & 15);
    const int lc   = (l >> 4) * 2;
    const uint32_t smem_base = smem_u32(smd);
    const uint32_t sa = smem_base + (uint32_t)(lrow * 80 + lc * 16);
    const uint32_t sb = sa + (uint32_t)(H_MAT * 2);
    const __half* ag = A + (size_t)(m0 + lrow) * (size_t)K + lc * 8;
    const __half* bg = B + (size_t)(n0 + lrow) * (size_t)K + lc * 8;

    auto copy_chunk = [&](int c, int st) {
        const uint32_t off = (uint32_t)st * STAGE_B;
        const __half* a = ag + c * 32;
        const __half* b = bg + c * 32;
        cp16(sa + off, a);      cp16(sa + off + 16, a + 8);
        cp16(sb + off, b);      cp16(sb + off + 16, b + 8);
    };

    // ---- compute mapping: warp tile 64(m) x 32(n)
    const int wm = (w & 1) * 64;
    const int wn = (w >> 1) * 32;
    const uint32_t aoff = (uint32_t)((wm + (l & 15)) * 80 + (l >> 4) * 16);
    const uint32_t boff = (uint32_t)((wn + (l & 7) + ((l >> 4) << 3)) * 80
                                     + ((l >> 3) & 1) * 16);

    float acc[4][4][4];
#pragma unroll
    for (int i = 0; i < 4; i++)
#pragma unroll
        for (int j = 0; j < 4; j++)
#pragma unroll
            for (int q = 0; q < 4; q++) acc[i][j][q] = 0.0f;

    const int nch = K / 32;          // >= 8 for all shapes here

    // prologue: stages 0,1,2 <- chunks 0,1,2
    copy_chunk(0, 0); CP_COMMIT();
    copy_chunk(1, 1); CP_COMMIT();
    copy_chunk(2, 2); CP_COMMIT();

    int st_cmp = 0;
    int st_cpy = 3;
    for (int c = 0; c < nch; c++) {
        CP_WAIT(2);
        __syncthreads();

        if (c + 3 < nch) copy_chunk(c + 3, st_cpy);
        CP_COMMIT();

        const uint32_t aB = smem_base + (uint32_t)st_cmp * STAGE_B;
        const uint32_t bB = aB + (uint32_t)(H_MAT * 2);
#pragma unroll
        for (int s = 0; s < 2; s++) {
            uint32_t af[4][4];
#pragma unroll
            for (int ma = 0; ma < 4; ma++) {
                const uint32_t addr = aB + aoff + (uint32_t)(ma * 16 * 80 + s * 32);
                asm volatile(
                    "ldmatrix.sync.aligned.m8n8.x4.shared.b16 {%0,%1,%2,%3}, [%4];"
                    : "=r"(af[ma][0]), "=r"(af[ma][1]),
                      "=r"(af[ma][2]), "=r"(af[ma][3])
                    : "r"(addr));
            }
            uint32_t bq[2][4];
#pragma unroll
            for (int p = 0; p < 2; p++) {
                const uint32_t addr = bB + boff + (uint32_t)(p * 16 * 80 + s * 32);
                asm volatile(
                    "ldmatrix.sync.aligned.m8n8.x4.shared.b16 {%0,%1,%2,%3}, [%4];"
                    : "=r"(bq[p][0]), "=r"(bq[p][1]),
                      "=r"(bq[p][2]), "=r"(bq[p][3])
                    : "r"(addr));
            }
#pragma unroll
            for (int ma = 0; ma < 4; ma++)
#pragma unroll
                for (int na = 0; na < 4; na++) {
                    const uint32_t b0 = bq[na >> 1][(na & 1) * 2];
                    const uint32_t b1 = bq[na >> 1][(na & 1) * 2 + 1];
                    asm volatile(
                        "mma.sync.aligned.m16n8k16.row.col.f32.f16.f16.f32 "
                        "{%0,%1,%2,%3}, {%4,%5,%6,%7}, {%8,%9}, {%0,%1,%2,%3};"
                        : "+f"(acc[ma][na][0]), "+f"(acc[ma][na][1]),
                          "+f"(acc[ma][na][2]), "+f"(acc[ma][na][3])
                        : "r"(af[ma][0]), "r"(af[ma][1]),
                          "r"(af[ma][2]), "r"(af[ma][3]),
                          "r"(b0), "r"(b1));
                }
        }
        st_cmp = (st_cmp == NSTAGE - 1) ? 0 : st_cmp + 1;
        st_cpy = (st_cpy == NSTAGE - 1) ? 0 : st_cpy + 1;
    }

    // ---- epilogue
    const int erow = m0 + wm + (l >> 2);
    const int ecol = n0 + wn + (l & 3) * 2;
#pragma unroll
    for (int ma = 0; ma < 4; ma++) {
        const int r = erow + ma * 16;
#pragma unroll
        for (int na = 0; na < 4; na++) {
            const int cc = ecol + na * 8;
            float2 bb = make_float2(0.f, 0.f);
            if (bias) bb = *(const float2*)(bias + cc);
            float lx = alpha * acc[ma][na][0] + bb.x;
            float ly = alpha * acc[ma][na][1] + bb.y;
            float hx = alpha * acc[ma][na][2] + bb.x;
            float hy = alpha * acc[ma][na][3] + bb.y;
            if (relu) {
                lx = fmaxf(lx, 0.f); ly = fmaxf(ly, 0.f);
                hx = fmaxf(hx, 0.f); hy = fmaxf(hy, 0.f);
            }
            if (!transC) {
                store2(C, (size_t)r * (size_t)N + cc, lx, ly);
                store2(C, (size_t)(r + 8) * (size_t)N + cc, hx, hy);
            } else {
                // C^T layout [batch][N][4096]; rows r are (b*4096 + t)
                const size_t b0 = ((size_t)(r >> 12) * 256 + cc) * 4096 + (r & 4095);
                C[b0]        = (TOut)lx;
                C[b0 + 4096] = (TOut)ly;
                const int r8 = r + 8;
                const size_t b1 = ((size_t)(r8 >> 12) * 256 + cc) * 4096 + (r8 & 4095);
                C[b1]        = (TOut)hx;
                C[b1 + 4096] = (TOut)hy;
            }
        }
    }
}

// Generic batched GEMM kernel (AV, MLP layers)
template <typename TOut>
__global__ void __launch_bounds__(256, 2) gemm_h_nt(
    const __half* __restrict__ A, const __half* __restrict__ B,
    const float* __restrict__ bias, TOut* __restrict__ C,
    int N, int K,
    long long sA, long long sB, long long sC,
    float alpha, int relu)
{
    extern __shared__ __align__(16) __half smd[];
    A += (size_t)blockIdx.z * (size_t)sA;
    B += (size_t)blockIdx.z * (size_t)sB;
    C += (size_t)blockIdx.z * (size_t)sC;
    gemm_core<TOut>(A, B, bias, C, N, K, alpha, relu, 0, smd,
                    blockIdx.y * 128, blockIdx.x * 128);
}

// Fused q/k projections: grid.z selects {q, k}.
__global__ void __launch_bounds__(256, 2) qk_proj(
    const __half* __restrict__ qh, const __half* __restrict__ xh,
    const __half* __restrict__ wh,
    const float* __restrict__ bq, const float* __restrict__ bk,
    __half* __restrict__ q, __half* __restrict__ k)
{
    extern __shared__ __align__(16) __half smd[];
    const int z = blockIdx.z;
    gemm_core<__half>(z == 0 ? qh : xh, wh + z * 65536,
                      z == 0 ? bq : bk, z == 0 ? q : k,
                      256, 256, 1.0f, 0, 0, smd,
                      blockIdx.y * 128, blockIdx.x * 128);
}

// QK^T (z = 0..3: batch slices) merged with the V projection (z = 4):
// v-proj is off the critical path and fills QKT's scheduling slack.
__global__ void __launch_bounds__(256, 2) qkt_vproj(
    const __half* __restrict__ q, const __half* __restrict__ k,
    __half* __restrict__ ah,
    const __half* __restrict__ xh, const __half* __restrict__ wv,
    const float* __restrict__ bv, __half* __restrict__ vt)
{
    extern __shared__ __align__(16) __half smd[];
    const int z = blockIdx.z;
    if (z < 4) {
        gemm_core<__half>(q + (size_t)z * 4096 * 256,
                          k + (size_t)z * 4096 * 256, nullptr,
                          ah + (size_t)z * 4096 * 4096,
                          4096, 256, 0.0625f, 0, 0, smd,
                          blockIdx.y * 128, blockIdx.x * 128);
    } else {
        const int id = blockIdx.y * 32 + blockIdx.x;   // 0..1023; need 256
        if (id >= 256) return;
        gemm_core<__half>(xh, wv, bv, vt,
                          256, 256, 1.0f, 0, 1, smd,
                          (id >> 1) * 128, (id & 1) * 128);
    }
}

// ===========================================================================
// One-shot fp32 -> fp16 conversion of query, x, and the 6 weights.
// Segments (in 8-elem units): query 524288 | x 524288 | 6 x 8192
// ===========================================================================
__global__ void __launch_bounds__(256) f2h_all(
    const float* __restrict__ query, const float* __restrict__ x,
    const float* __restrict__ Wq, const float* __restrict__ Wk,
    const float* __restrict__ Wv, const float* __restrict__ W1,
    const float* __restrict__ W2, const float* __restrict__ W3,
    __half* __restrict__ qh, __half* __restrict__ xh, __half* __restrict__ wh)
{
    const int idx = blockIdx.x * 256 + threadIdx.x;    // vec8 index
    const float* s;
    __half* d;
    int off;
    if (idx < 524288)            { s = query; d = qh; off = idx; }
    else if (idx < 1048576)      { s = x;     d = xh; off = idx - 524288; }
    else {
        const int wv8 = idx - 1048576;                 // 0 .. 49151
        const int wi = wv8 >> 13;                      // weight id 0..5
        off = wv8 & 8191;
        switch (wi) {
            case 0: s = Wq; break;  case 1: s = Wk; break;
            case 2: s = Wv; break;  case 3: s = W1; break;
            case 4: s = W2; break;  default: s = W3; break;
        }
        d = wh + wi * 65536;
    }
    const int i = off * 8;
    float4 u = *(const float4*)(s + i);
    float4 v = *(const float4*)(s + i + 4);
    uint4 o;
    o.x = f2h2(u.x, u.y); o.y = f2h2(u.z, u.w);
    o.z = f2h2(v.x, v.y); o.w = f2h2(v.z, v.w);
    *(uint4*)(d + i) = o;
}

// ---------------------------------------------------------------------------
// Row softmax: reads fp16 scores from ah, writes fp32 attn (output slot) and
// fp16 attn back into ah (for AV). attn[16384][4096].
// ---------------------------------------------------------------------------
static __device__ __forceinline__ float warpMax(float v) {
#pragma unroll
    for (int o = 16; o > 0; o >>= 1) v = fmaxf(v, __shfl_xor_sync(0xffffffffu, v, o));
    return v;
}
static __device__ __forceinline__ float warpSum(float v) {
#pragma unroll
    for (int o = 16; o > 0; o >>= 1) v += __shfl_xor_sync(0xffffffffu, v, o);
    return v;
}

__global__ void __launch_bounds__(256) softmax_rows(
    float* __restrict__ attn, __half* __restrict__ ah)
{
    __shared__ float red[8];
    __shared__ float bcast;
    const size_t row = blockIdx.x;
    float* p = attn + row * 4096;
    __half2* ph = (__half2*)(ah + row * 4096);
    const int tid = threadIdx.x;

    float v[16];
#pragma unroll
    for (int j = 0; j < 8; j++) {
        const float2 f = __half22float2(ph[tid + j * 256]);
        v[2 * j]     = f.x;
        v[2 * j + 1] = f.y;
    }

    float m = v[0];
#pragma unroll
    for (int i = 1; i < 16; i++) m = fmaxf(m, v[i]);
    m = warpMax(m);
    if ((tid & 31) == 0) red[tid >> 5] = m;
    __syncthreads();
    if (tid < 32) {
        float t = (tid < 8) ? red[tid] : -3.4e38f;
        t = warpMax(t);
        if (tid == 0) bcast = t;
    }
    __syncthreads();
    m = bcast;

    float s = 0.0f;
#pragma unroll
    for (int i = 0; i < 16; i++) { v[i] = __expf(v[i] - m); s += v[i]; }
    s = warpSum(s);
    __syncthreads();
    if ((tid & 31) == 0) red[tid >> 5] = s;
    __syncthreads();
    if (tid < 32) {
        float t = (tid < 8) ? red[tid] : 0.0f;
        t = warpSum(t);
        if (tid == 0) bcast = t;
    }
    __syncthreads();
    const float inv = 1.0f / bcast;
#pragma unroll
    for (int j = 0; j < 8; j++) {
        const float r0 = v[2 * j] * inv;
        const float r1 = v[2 * j + 1] * inv;
        *(float2*)(p + 2 * (tid + j * 256)) = make_float2(r0, r1);
        ph[tid + j * 256] = __floats2half2_rn(r0, r1);
    }
}

// ---------------------------------------------------------------------------
// Host launcher (graph-capturable: kernel launches only)
// ---------------------------------------------------------------------------
extern "C" void kernel_launch(void* const* d_in, const int* in_sizes, int n_in,
                              void* d_out, int out_size)
{
    (void)in_sizes; (void)n_in; (void)out_size;
    const float* x     = (const float*)d_in[0];
    const float* query = (const float*)d_in[1];
    const float* Wq = (const float*)d_in[2];  const float* bq = (const float*)d_in[3];
    const float* Wk = (const float*)d_in[4];  const float* bk = (const float*)d_in[5];
    const float* Wv = (const float*)d_in[6];  const float* bv = (const float*)d_in[7];
    const float* W1 = (const float*)d_in[8];  const float* b1 = (const float*)d_in[9];
    const float* W2 = (const float*)d_in[10]; const float* b2 = (const float*)d_in[11];
    const float* W3 = (const float*)d_in[12]; const float* b3 = (const float*)d_in[13];

    float* outp = (float*)d_out;
    float* hout = outp;                                    // [4,4096,256]
    float* attn = outp + (size_t)4 * 4096 * 256;           // [4,4096,4096]

    __half *xh, *qh, *q, *k, *vt, *t0, *t1, *wh, *ah;
    cudaGetSymbolAddress((void**)&xh, g_xh);
    cudaGetSymbolAddress((void**)&qh, g_qh);
    cudaGetSymbolAddress((void**)&q,  g_q);
    cudaGetSymbolAddress((void**)&k,  g_k);
    cudaGetSymbolAddress((void**)&vt, g_vt);
    cudaGetSymbolAddress((void**)&t0, g_t0);
    cudaGetSymbolAddress((void**)&t1, g_t1);
    cudaGetSymbolAddress((void**)&wh, g_w);
    cudaGetSymbolAddress((void**)&ah, g_ah);

    cudaFuncSetAttribute(gemm_h_nt<__half>,
                         cudaFuncAttributeMaxDynamicSharedMemorySize, GEMM_SMEM);
    cudaFuncSetAttribute(gemm_h_nt<float>,
                         cudaFuncAttributeMaxDynamicSharedMemorySize, GEMM_SMEM);
    cudaFuncSetAttribute(qk_proj,
                         cudaFuncAttributeMaxDynamicSharedMemorySize, GEMM_SMEM);
    cudaFuncSetAttribute(qkt_vproj,
                         cudaFuncAttributeMaxDynamicSharedMemorySize, GEMM_SMEM);

    const int Mtot = 4 * 4096;
    const int S = 4096;
    const dim3 blk(256);
    const dim3 gLin(2, Mtot / 128, 1);          // (2, 128, 1)

    // ---- one-shot fp32 -> fp16 conversions (query, x, 6 weights)
    f2h_all<<<4288, 256>>>(query, x, Wq, Wk, Wv, W1, W2, W3, qh, xh, wh);

    // ---- q/k projections
    qk_proj<<<dim3(2, 128, 2), blk, GEMM_SMEM>>>(qh, xh, wh, bq, bk, q, k);

    // ---- scores = (q @ k^T)/sqrt(D) -> fp16 ah; V-proj (z=4) rides along
    qkt_vproj<<<dim3(32, 32, 5), blk, GEMM_SMEM>>>(
        q, k, ah, xh, wh + 2 * 65536, bv, vt);

    // ---- softmax: fp16 scores -> fp32 attn output + fp16 attn (in ah)
    softmax_rows<<<Mtot, blk>>>(attn, ah);

    // ---- out = attn @ V = attn_h @ (V^T)^T  (fp16 out)
    gemm_h_nt<__half><<<dim3(2, S / 128, 4), blk, GEMM_SMEM>>>(
        ah, vt, nullptr, t0, 256, S,
        (long long)S * S, (long long)256 * S, (long long)S * 256, 1.0f, 0);

    // ---- MLP: three relu(linear) layers; last writes fp32 h output
    gemm_h_nt<__half><<<gLin, blk, GEMM_SMEM>>>(t0, wh + 3 * 65536, b1, t1,
                                                256, 256, 0, 0, 0, 1.0f, 1);
    gemm_h_nt<__half><<<gLin, blk, GEMM_SMEM>>>(t1, wh + 4 * 65536, b2, t0,
                                                256, 256, 0, 0, 0, 1.0f, 1);
    gemm_h_nt<float ><<<gLin, blk, GEMM_SMEM>>>(t0, wh + 5 * 65536, b3, hout,
                                                256, 256, 0, 0, 0, 1.0f, 1);
}